// round 5
// baseline (speedup 1.0000x reference)
#include <cuda_runtime.h>

// Problem constants
#define BATCH 32
#define SEQ   2048
#define NPOS  (BATCH * SEQ)   // 65536 positions
#define M     10              // number of primes
#define NTAB  129             // sum of primes 2+3+5+7+11+13+17+19+23+29

// Tables (filled every launch by init kernel; deterministic, graph-capturable)
// g_tabW: { K*cos, K*cos, K*sin, K*sin }  with K = TEMP * log2(e)  (softmax logits in log2 domain)
// g_tabE: { cos, sin }                    (re-encode templates)
__device__ float4 g_tabW[NTAB];
__device__ float2 g_tabE[NTAB];

__global__ void init_tables_kernel() {
    int idx = threadIdx.x;
    if (idx >= NTAB) return;
    const int primes[M] = {2, 3, 5, 7, 11, 13, 17, 19, 23, 29};
    int k = idx, p = 29;
    for (int pi = 0; pi < M; pi++) {
        if (k < primes[pi]) { p = primes[pi]; break; }
        k -= primes[pi];
    }
    double ang = 6.283185307179586476925287 * (double)k / (double)p;
    float c = (float)cos(ang), s = (float)sin(ang);  // matches numpy f64->f32 rounding
    const double K = 1000.0 * 1.4426950408889634074; // TEMP * log2(e)
    float cK = (float)((double)c * K);
    float sK = (float)((double)s * K);
    g_tabW[idx] = make_float4(cK, cK, sK, sK);
    g_tabE[idx] = make_float2(c, s);
}

// ---- packed f32x2 helpers (Blackwell FFMA2; only reachable via PTX) ----
union F2U { float2 f; unsigned long long u; };

__device__ __forceinline__ float2 f2fma(float2 a, float2 b, float2 c) {
    F2U A, B, C, D; A.f = a; B.f = b; C.f = c;
    asm("fma.rn.f32x2 %0, %1, %2, %3;" : "=l"(D.u) : "l"(A.u), "l"(B.u), "l"(C.u));
    return D.f;
}
__device__ __forceinline__ float2 f2mul(float2 a, float2 b) {
    F2U A, B, D; A.f = a; B.f = b;
    asm("mul.rn.f32x2 %0, %1, %2;" : "=l"(D.u) : "l"(A.u), "l"(B.u));
    return D.f;
}
__device__ __forceinline__ float2 f2add(float2 a, float2 b) {
    F2U A, B, D; A.f = a; B.f = b;
    asm("add.rn.f32x2 %0, %1, %2;" : "=l"(D.u) : "l"(A.u), "l"(B.u));
    return D.f;
}
__device__ __forceinline__ float ex2f(float x) {
    float r; asm("ex2.approx.f32 %0, %1;" : "=f"(r) : "f"(x)); return r;
}
__device__ __forceinline__ float rcpf(float x) {
    float r; asm("rcp.approx.f32 %0, %1;" : "=f"(r) : "f"(x)); return r;
}

__device__ __forceinline__ void emit_addsub(float2 A, float2 B, float2* oAdd, float2* oSub, int idx) {
    float t1 = A.x * B.x, t2 = A.y * B.y, t3 = A.y * B.x, t4 = A.x * B.y;
    oAdd[idx] = make_float2(t1 - t2, t3 + t4);
    oSub[idx] = make_float2(t1 + t2, t3 - t4);
}

// ---- packed-lane path: a/b sides in the two f32x2 lanes ----
template <int P, int PI, int OFF>
__device__ __forceinline__ void prime_packed(
    int pos, const float2* __restrict__ a2, const float2* __restrict__ b2,
    float2* __restrict__ oAdd, float2* __restrict__ oSub, float2* __restrict__ oMul,
    const float4* __restrict__ shW, const float2* __restrict__ shE)
{
    const int idx = pos * M + PI;
    const float2 A = a2[idx], B = b2[idx];
    emit_addsub(A, B, oAdd, oSub, idx);

    const float2 c2 = make_float2(A.x, B.x);
    const float2 s2 = make_float2(A.y, B.y);

    // logits in log2 domain (tables pre-scaled by TEMP*log2e)
    float2 w[P];
#pragma unroll
    for (int i = 0; i < P; i++) {
        float4 t = shW[OFF + i];
        w[i] = f2fma(c2, make_float2(t.x, t.y), f2mul(s2, make_float2(t.z, t.w)));
    }

    // dual-accumulator max per lane
    float a0 = w[0].x, b0 = w[0].y;
    float a1 = (P > 1) ? w[1].x : w[0].x;
    float b1 = (P > 1) ? w[1].y : w[0].y;
#pragma unroll
    for (int i = 2; i < P; i++) {
        if (i & 1) { a1 = fmaxf(a1, w[i].x); b1 = fmaxf(b1, w[i].y); }
        else       { a0 = fmaxf(a0, w[i].x); b0 = fmaxf(b0, w[i].y); }
    }
    const float2 nm = make_float2(-fmaxf(a0, a1), -fmaxf(b0, b1));

    // exp2 + packed sums, dual accumulators
    float2 s0 = make_float2(0.f, 0.f), s1 = make_float2(0.f, 0.f);
#pragma unroll
    for (int i = 0; i < P; i++) {
        float2 arg = f2add(w[i], nm);
        w[i] = make_float2(ex2f(arg.x), ex2f(arg.y));
        if (i & 1) s1 = f2add(s1, w[i]); else s0 = f2add(s0, w[i]);
    }
    const float2 S = f2add(s0, s1);
    const float Sa = S.x, Sb = S.y;

    // dist; residue-0 closed form for i=0 / j=0 cross terms
    float dist[P];
    dist[0] = fmaf(w[0].x, Sb, fmaf(w[0].y, Sa, -(w[0].x * w[0].y)));
#pragma unroll
    for (int k = 1; k < P; k++) dist[k] = 0.f;
#pragma unroll
    for (int i = 1; i < P; i++) {
        const float wai = w[i].x;
#pragma unroll
        for (int j = 1; j < P; j++) {
            const int k = (i * j) % P;   // bijection over 1..P-1 per i
            dist[k] = fmaf(wai, w[j].y, dist[k]);
        }
    }

    // re-encode + normalize
    float X0 = 0.f, X1 = 0.f, Y0 = 0.f, Y1 = 0.f;
#pragma unroll
    for (int k = 0; k < P; k++) {
        float2 e = shE[OFF + k];
        if (k & 1) { X1 = fmaf(dist[k], e.x, X1); Y1 = fmaf(dist[k], e.y, Y1); }
        else       { X0 = fmaf(dist[k], e.x, X0); Y0 = fmaf(dist[k], e.y, Y0); }
    }
    const float inv = rcpf(Sa * Sb);
    oMul[idx] = make_float2((X0 + X1) * inv, (Y0 + Y1) * inv);
}

// ---- low-register path (large primes): store only wb; recompute wa per outer-i ----
template <int P, int PI, int OFF>
__device__ __forceinline__ void prime_lowreg(
    int pos, const float2* __restrict__ a2, const float2* __restrict__ b2,
    float2* __restrict__ oAdd, float2* __restrict__ oSub, float2* __restrict__ oMul,
    const float4* __restrict__ shW, const float2* __restrict__ shE)
{
    const int idx = pos * M + PI;
    const float2 A = a2[idx], B = b2[idx];
    emit_addsub(A, B, oAdd, oSub, idx);

    const float2 c2 = make_float2(A.x, B.x);
    const float2 s2 = make_float2(A.y, B.y);

    // pass 1: packed logits, packed max (no storage)
    float a0, a1, b0, b1;
    {
        float4 t0 = shW[OFF + 0];
        float2 l0 = f2fma(c2, make_float2(t0.x, t0.y), f2mul(s2, make_float2(t0.z, t0.w)));
        float4 t1 = shW[OFF + 1];
        float2 l1 = f2fma(c2, make_float2(t1.x, t1.y), f2mul(s2, make_float2(t1.z, t1.w)));
        a0 = l0.x; b0 = l0.y; a1 = l1.x; b1 = l1.y;
    }
#pragma unroll
    for (int i = 2; i < P; i++) {
        float4 t = shW[OFF + i];
        float2 l = f2fma(c2, make_float2(t.x, t.y), f2mul(s2, make_float2(t.z, t.w)));
        if (i & 1) { a1 = fmaxf(a1, l.x); b1 = fmaxf(b1, l.y); }
        else       { a0 = fmaxf(a0, l.x); b0 = fmaxf(b0, l.y); }
    }
    const float mxa = fmaxf(a0, a1), mxb = fmaxf(b0, b1);
    const float2 nm = make_float2(-mxa, -mxb);

    // pass 2: recompute logits, exp; store wb only; sums for both sides
    float wb[P];
    float Sa = 0.f, Sb = 0.f, wa0 = 0.f;
#pragma unroll
    for (int i = 0; i < P; i++) {
        float4 t = shW[OFF + i];
        float2 l = f2fma(c2, make_float2(t.x, t.y), f2mul(s2, make_float2(t.z, t.w)));
        float2 arg = f2add(l, nm);
        float wav = ex2f(arg.x);
        float wbv = ex2f(arg.y);
        if (i == 0) wa0 = wav;
        Sa += wav; Sb += wbv;
        wb[i] = wbv;
    }
    const float SaSb = Sa * Sb;

    // pass 3: dist with wa recomputed per outer-i (bit-identical rounding to pass 2)
    float dist[P];
    dist[0] = fmaf(wa0, Sb, fmaf(wb[0], Sa, -(wa0 * wb[0])));
#pragma unroll
    for (int k = 1; k < P; k++) dist[k] = 0.f;
#pragma unroll
    for (int i = 1; i < P; i++) {
        float4 t = shW[OFF + i];
        float la = fmaf(A.x, t.x, A.y * t.z);     // a-side logit (scalar)
        float wai = ex2f(la - mxa);
#pragma unroll
        for (int j = 1; j < P; j++) {
            const int k = (i * j) % P;
            dist[k] = fmaf(wai, wb[j], dist[k]);
        }
    }

    // re-encode + normalize
    float X0 = 0.f, X1 = 0.f, Y0 = 0.f, Y1 = 0.f;
#pragma unroll
    for (int k = 0; k < P; k++) {
        float2 e = shE[OFF + k];
        if (k & 1) { X1 = fmaf(dist[k], e.x, X1); Y1 = fmaf(dist[k], e.y, Y1); }
        else       { X0 = fmaf(dist[k], e.x, X0); Y0 = fmaf(dist[k], e.y, Y0); }
    }
    const float inv = rcpf(SaSb);
    oMul[idx] = make_float2((X0 + X1) * inv, (Y0 + Y1) * inv);
}

// 256 threads per block: warps 0-3 (grp 0) handle primes {2,3,5,19,29},
// warps 4-7 (grp 1) handle primes {7,11,13,17,23} for the SAME 128 positions.
// Balanced (~1651 vs ~1659 issue-ops/pos), warp-uniform branch, and all writes
// to any output cache line come from one block at one time (no partial-line RMW).
__global__ void __launch_bounds__(256, 4)
circle_kernel(const float* __restrict__ a, const float* __restrict__ b,
              float* __restrict__ out)
{
    __shared__ float4 shW[NTAB];
    __shared__ float2 shE[NTAB];
    for (int i = threadIdx.x; i < NTAB; i += 256) {
        shW[i] = g_tabW[i];
        shE[i] = g_tabE[i];
    }
    __syncthreads();

    const int tid = threadIdx.x;
    const int grp = tid >> 7;             // 0 or 1 (warp-uniform)
    const int pos = blockIdx.x * 128 + (tid & 127);

    const float2* a2 = (const float2*)a;
    const float2* b2 = (const float2*)b;
    float2* oAdd = (float2*)out;
    float2* oSub = oAdd + (size_t)NPOS * M;
    float2* oMul = oSub + (size_t)NPOS * M;

    // prime offsets into tables: 2:0 3:2 5:5 7:10 11:17 13:28 17:41 19:58 23:77 29:100
    if (grp == 0) {
        prime_packed< 2, 0,   0>(pos, a2, b2, oAdd, oSub, oMul, shW, shE);
        prime_packed< 3, 1,   2>(pos, a2, b2, oAdd, oSub, oMul, shW, shE);
        prime_packed< 5, 2,   5>(pos, a2, b2, oAdd, oSub, oMul, shW, shE);
        prime_packed<19, 7,  58>(pos, a2, b2, oAdd, oSub, oMul, shW, shE);
        prime_lowreg<29, 9, 100>(pos, a2, b2, oAdd, oSub, oMul, shW, shE);
    } else {
        prime_packed< 7, 3,  10>(pos, a2, b2, oAdd, oSub, oMul, shW, shE);
        prime_packed<11, 4,  17>(pos, a2, b2, oAdd, oSub, oMul, shW, shE);
        prime_packed<13, 5,  28>(pos, a2, b2, oAdd, oSub, oMul, shW, shE);
        prime_packed<17, 6,  41>(pos, a2, b2, oAdd, oSub, oMul, shW, shE);
        prime_lowreg<23, 8,  77>(pos, a2, b2, oAdd, oSub, oMul, shW, shE);
    }
}

extern "C" void kernel_launch(void* const* d_in, const int* in_sizes, int n_in,
                              void* d_out, int out_size) {
    const float* a = (const float*)d_in[0];
    const float* b = (const float*)d_in[1];
    float* out = (float*)d_out;
    init_tables_kernel<<<1, 160>>>();
    circle_kernel<<<NPOS / 128, 256>>>(a, b, out);
}

// round 7
// speedup vs baseline: 1.9261x; 1.9261x over previous
#include <cuda_runtime.h>

// Problem constants
#define BATCH 32
#define SEQ   2048
#define NPOS  (BATCH * SEQ)   // 65536 positions
#define M     10              // number of primes
#define NTAB  129             // sum of primes 2+3+5+7+11+13+17+19+23+29

// Tables (filled every launch by init kernel; deterministic, graph-capturable)
// g_tabW: { K*cos, K*cos, K*sin, K*sin }  with K = TEMP * log2(e)  (softmax logits in log2 domain)
// g_tabE: { cos, sin }                    (re-encode templates)
__device__ float4 g_tabW[NTAB];
__device__ float2 g_tabE[NTAB];

__global__ void init_tables_kernel() {
    int idx = threadIdx.x;
    if (idx >= NTAB) return;
    const int primes[M] = {2, 3, 5, 7, 11, 13, 17, 19, 23, 29};
    int k = idx, p = 29;
    for (int pi = 0; pi < M; pi++) {
        if (k < primes[pi]) { p = primes[pi]; break; }
        k -= primes[pi];
    }
    double ang = 6.283185307179586476925287 * (double)k / (double)p;
    float c = (float)cos(ang), s = (float)sin(ang);  // matches numpy f64->f32 rounding
    const double K = 1000.0 * 1.4426950408889634074; // TEMP * log2(e)
    float cK = (float)((double)c * K);
    float sK = (float)((double)s * K);
    g_tabW[idx] = make_float4(cK, cK, sK, sK);
    g_tabE[idx] = make_float2(c, s);
}

// ---- packed f32x2 helpers (Blackwell FFMA2; only reachable via PTX) ----
union F2U { float2 f; unsigned long long u; };

__device__ __forceinline__ float2 f2fma(float2 a, float2 b, float2 c) {
    F2U A, B, C, D; A.f = a; B.f = b; C.f = c;
    asm("fma.rn.f32x2 %0, %1, %2, %3;" : "=l"(D.u) : "l"(A.u), "l"(B.u), "l"(C.u));
    return D.f;
}
__device__ __forceinline__ float2 f2mul(float2 a, float2 b) {
    F2U A, B, D; A.f = a; B.f = b;
    asm("mul.rn.f32x2 %0, %1, %2;" : "=l"(D.u) : "l"(A.u), "l"(B.u));
    return D.f;
}
__device__ __forceinline__ float2 f2add(float2 a, float2 b) {
    F2U A, B, D; A.f = a; B.f = b;
    asm("add.rn.f32x2 %0, %1, %2;" : "=l"(D.u) : "l"(A.u), "l"(B.u));
    return D.f;
}
__device__ __forceinline__ float ex2f(float x) {
    float r; asm("ex2.approx.f32 %0, %1;" : "=f"(r) : "f"(x)); return r;
}
__device__ __forceinline__ float rcpf(float x) {
    float r; asm("rcp.approx.f32 %0, %1;" : "=f"(r) : "f"(x)); return r;
}

__device__ __forceinline__ void emit_addsub(float2 A, float2 B, float2* oAdd, float2* oSub, int idx) {
    float t1 = A.x * B.x, t2 = A.y * B.y, t3 = A.y * B.x, t4 = A.x * B.y;
    oAdd[idx] = make_float2(t1 - t2, t3 + t4);
    oSub[idx] = make_float2(t1 + t2, t3 - t4);
}

// ---- packed-lane path: a/b sides in the two f32x2 lanes ----
template <int P, int PI, int OFF>
__device__ __forceinline__ void prime_packed(
    int pos, const float2* __restrict__ a2, const float2* __restrict__ b2,
    float2* __restrict__ oAdd, float2* __restrict__ oSub, float2* __restrict__ oMul,
    const float4* __restrict__ shW, const float2* __restrict__ shE)
{
    const int idx = pos * M + PI;
    const float2 A = a2[idx], B = b2[idx];
    emit_addsub(A, B, oAdd, oSub, idx);

    const float2 c2 = make_float2(A.x, B.x);
    const float2 s2 = make_float2(A.y, B.y);

    // logits in log2 domain (tables pre-scaled by TEMP*log2e)
    float2 w[P];
#pragma unroll
    for (int i = 0; i < P; i++) {
        float4 t = shW[OFF + i];
        w[i] = f2fma(c2, make_float2(t.x, t.y), f2mul(s2, make_float2(t.z, t.w)));
    }

    // dual-accumulator max per lane
    float a0 = w[0].x, b0 = w[0].y;
    float a1 = (P > 1) ? w[1].x : w[0].x;
    float b1 = (P > 1) ? w[1].y : w[0].y;
#pragma unroll
    for (int i = 2; i < P; i++) {
        if (i & 1) { a1 = fmaxf(a1, w[i].x); b1 = fmaxf(b1, w[i].y); }
        else       { a0 = fmaxf(a0, w[i].x); b0 = fmaxf(b0, w[i].y); }
    }
    const float2 nm = make_float2(-fmaxf(a0, a1), -fmaxf(b0, b1));

    // exp2 + packed sums, dual accumulators
    float2 s0 = make_float2(0.f, 0.f), s1 = make_float2(0.f, 0.f);
#pragma unroll
    for (int i = 0; i < P; i++) {
        float2 arg = f2add(w[i], nm);
        w[i] = make_float2(ex2f(arg.x), ex2f(arg.y));
        if (i & 1) s1 = f2add(s1, w[i]); else s0 = f2add(s0, w[i]);
    }
    const float2 S = f2add(s0, s1);
    const float Sa = S.x, Sb = S.y;

    // dist; residue-0 closed form for i=0 / j=0 cross terms
    float dist[P];
    dist[0] = fmaf(w[0].x, Sb, fmaf(w[0].y, Sa, -(w[0].x * w[0].y)));
#pragma unroll
    for (int k = 1; k < P; k++) dist[k] = 0.f;
#pragma unroll
    for (int i = 1; i < P; i++) {
        const float wai = w[i].x;
#pragma unroll
        for (int j = 1; j < P; j++) {
            const int k = (i * j) % P;   // bijection over 1..P-1 per i
            dist[k] = fmaf(wai, w[j].y, dist[k]);
        }
    }

    // re-encode + normalize
    float X0 = 0.f, X1 = 0.f, Y0 = 0.f, Y1 = 0.f;
#pragma unroll
    for (int k = 0; k < P; k++) {
        float2 e = shE[OFF + k];
        if (k & 1) { X1 = fmaf(dist[k], e.x, X1); Y1 = fmaf(dist[k], e.y, Y1); }
        else       { X0 = fmaf(dist[k], e.x, X0); Y0 = fmaf(dist[k], e.y, Y0); }
    }
    const float inv = rcpf(Sa * Sb);
    oMul[idx] = make_float2((X0 + X1) * inv, (Y0 + Y1) * inv);
}

// ---- low-register path (large primes): store only wb; recompute wa per outer-i ----
template <int P, int PI, int OFF>
__device__ __forceinline__ void prime_lowreg(
    int pos, const float2* __restrict__ a2, const float2* __restrict__ b2,
    float2* __restrict__ oAdd, float2* __restrict__ oSub, float2* __restrict__ oMul,
    const float4* __restrict__ shW, const float2* __restrict__ shE)
{
    const int idx = pos * M + PI;
    const float2 A = a2[idx], B = b2[idx];
    emit_addsub(A, B, oAdd, oSub, idx);

    const float2 c2 = make_float2(A.x, B.x);
    const float2 s2 = make_float2(A.y, B.y);

    // pass 1: packed logits, packed max (no storage)
    float a0, a1, b0, b1;
    {
        float4 t0 = shW[OFF + 0];
        float2 l0 = f2fma(c2, make_float2(t0.x, t0.y), f2mul(s2, make_float2(t0.z, t0.w)));
        float4 t1 = shW[OFF + 1];
        float2 l1 = f2fma(c2, make_float2(t1.x, t1.y), f2mul(s2, make_float2(t1.z, t1.w)));
        a0 = l0.x; b0 = l0.y; a1 = l1.x; b1 = l1.y;
    }
#pragma unroll
    for (int i = 2; i < P; i++) {
        float4 t = shW[OFF + i];
        float2 l = f2fma(c2, make_float2(t.x, t.y), f2mul(s2, make_float2(t.z, t.w)));
        if (i & 1) { a1 = fmaxf(a1, l.x); b1 = fmaxf(b1, l.y); }
        else       { a0 = fmaxf(a0, l.x); b0 = fmaxf(b0, l.y); }
    }
    const float mxa = fmaxf(a0, a1), mxb = fmaxf(b0, b1);
    const float2 nm = make_float2(-mxa, -mxb);

    // pass 2: recompute logits, exp; store wb only; sums for both sides
    float wb[P];
    float Sa = 0.f, Sb = 0.f, wa0 = 0.f;
#pragma unroll
    for (int i = 0; i < P; i++) {
        float4 t = shW[OFF + i];
        float2 l = f2fma(c2, make_float2(t.x, t.y), f2mul(s2, make_float2(t.z, t.w)));
        float2 arg = f2add(l, nm);
        float wav = ex2f(arg.x);
        float wbv = ex2f(arg.y);
        if (i == 0) wa0 = wav;
        Sa += wav; Sb += wbv;
        wb[i] = wbv;
    }
    const float SaSb = Sa * Sb;

    // pass 3: dist with wa recomputed per outer-i (bit-identical rounding to pass 2)
    float dist[P];
    dist[0] = fmaf(wa0, Sb, fmaf(wb[0], Sa, -(wa0 * wb[0])));
#pragma unroll
    for (int k = 1; k < P; k++) dist[k] = 0.f;
#pragma unroll
    for (int i = 1; i < P; i++) {
        float4 t = shW[OFF + i];
        float la = fmaf(A.x, t.x, A.y * t.z);     // a-side logit (scalar)
        float wai = ex2f(la - mxa);
#pragma unroll
        for (int j = 1; j < P; j++) {
            const int k = (i * j) % P;
            dist[k] = fmaf(wai, wb[j], dist[k]);
        }
    }

    // re-encode + normalize
    float X0 = 0.f, X1 = 0.f, Y0 = 0.f, Y1 = 0.f;
#pragma unroll
    for (int k = 0; k < P; k++) {
        float2 e = shE[OFF + k];
        if (k & 1) { X1 = fmaf(dist[k], e.x, X1); Y1 = fmaf(dist[k], e.y, Y1); }
        else       { X0 = fmaf(dist[k], e.x, X0); Y0 = fmaf(dist[k], e.y, Y0); }
    }
    const float inv = rcpf(SaSb);
    oMul[idx] = make_float2((X0 + X1) * inv, (Y0 + Y1) * inv);
}

// 256 threads per block: warps 0-3 (grp 0) handle primes {2,3,5,19,29},
// warps 4-7 (grp 1) handle primes {7,11,13,17,23} for the SAME 128 positions.
// Balanced (~1651 vs ~1659 issue-ops/pos), warp-uniform branch, and all writes
// to any output cache line come from one block at one time (no partial-line RMW).
// launch_bounds (256,3) -> 85-reg cap: both prime paths fit WITHOUT spilling
// (the (256,4)/64-reg version spilled the p>=19 loops to local memory).
__global__ void __launch_bounds__(256, 3)
circle_kernel(const float* __restrict__ a, const float* __restrict__ b,
              float* __restrict__ out)
{
    __shared__ float4 shW[NTAB];
    __shared__ float2 shE[NTAB];
    for (int i = threadIdx.x; i < NTAB; i += 256) {
        shW[i] = g_tabW[i];
        shE[i] = g_tabE[i];
    }
    __syncthreads();

    const int tid = threadIdx.x;
    const int grp = tid >> 7;             // 0 or 1 (warp-uniform)
    const int pos = blockIdx.x * 128 + (tid & 127);

    const float2* a2 = (const float2*)a;
    const float2* b2 = (const float2*)b;
    float2* oAdd = (float2*)out;
    float2* oSub = oAdd + (size_t)NPOS * M;
    float2* oMul = oSub + (size_t)NPOS * M;

    // prime offsets into tables: 2:0 3:2 5:5 7:10 11:17 13:28 17:41 19:58 23:77 29:100
    if (grp == 0) {
        prime_packed< 2, 0,   0>(pos, a2, b2, oAdd, oSub, oMul, shW, shE);
        prime_packed< 3, 1,   2>(pos, a2, b2, oAdd, oSub, oMul, shW, shE);
        prime_packed< 5, 2,   5>(pos, a2, b2, oAdd, oSub, oMul, shW, shE);
        prime_packed<19, 7,  58>(pos, a2, b2, oAdd, oSub, oMul, shW, shE);
        prime_lowreg<29, 9, 100>(pos, a2, b2, oAdd, oSub, oMul, shW, shE);
    } else {
        prime_packed< 7, 3,  10>(pos, a2, b2, oAdd, oSub, oMul, shW, shE);
        prime_packed<11, 4,  17>(pos, a2, b2, oAdd, oSub, oMul, shW, shE);
        prime_packed<13, 5,  28>(pos, a2, b2, oAdd, oSub, oMul, shW, shE);
        prime_packed<17, 6,  41>(pos, a2, b2, oAdd, oSub, oMul, shW, shE);
        prime_lowreg<23, 8,  77>(pos, a2, b2, oAdd, oSub, oMul, shW, shE);
    }
}

extern "C" void kernel_launch(void* const* d_in, const int* in_sizes, int n_in,
                              void* d_out, int out_size) {
    const float* a = (const float*)d_in[0];
    const float* b = (const float*)d_in[1];
    float* out = (float*)d_out;
    init_tables_kernel<<<1, 160>>>();
    circle_kernel<<<NPOS / 128, 256>>>(a, b, out);
}

// round 8
// speedup vs baseline: 2.4641x; 1.2793x over previous
#include <cuda_runtime.h>

// Problem constants
#define BATCH 32
#define SEQ   2048
#define NPOS  (BATCH * SEQ)   // 65536 positions
#define M     10              // number of primes
#define NTAB  129             // sum of primes 2+3+5+7+11+13+17+19+23+29

// Tables (filled every launch by init kernel; deterministic, graph-capturable)
// g_tabW: { K*cos, K*sin }  with K = TEMP * log2(e)  (softmax logits in log2 domain)
// g_tabE: { cos, sin }      (re-encode templates)
__device__ float2 g_tabW[NTAB];
__device__ float2 g_tabE[NTAB];

__global__ void init_tables_kernel() {
    int idx = threadIdx.x;
    if (idx >= NTAB) return;
    const int primes[M] = {2, 3, 5, 7, 11, 13, 17, 19, 23, 29};
    int k = idx, p = 29;
    for (int pi = 0; pi < M; pi++) {
        if (k < primes[pi]) { p = primes[pi]; break; }
        k -= primes[pi];
    }
    double ang = 6.283185307179586476925287 * (double)k / (double)p;
    float c = (float)cos(ang), s = (float)sin(ang);  // matches numpy f64->f32 rounding
    const double K = 1000.0 * 1.4426950408889634074; // TEMP * log2(e)
    g_tabW[idx] = make_float2((float)((double)c * K), (float)((double)s * K));
    g_tabE[idx] = make_float2(c, s);
}

__device__ __forceinline__ float ex2f(float x) {
    float r; asm("ex2.approx.f32 %0, %1;" : "=f"(r) : "f"(x)); return r;
}
__device__ __forceinline__ float rcpf(float x) {
    float r; asm("rcp.approx.f32 %0, %1;" : "=f"(r) : "f"(x)); return r;
}

// One prime, one position, fully scalar (no f32x2 register-pair constraints).
template <int P, int PI, int OFF>
__device__ __forceinline__ void prime_scalar(
    int pos, const float2* __restrict__ a2, const float2* __restrict__ b2,
    float2* __restrict__ oAdd, float2* __restrict__ oSub, float2* __restrict__ oMul,
    const float2* __restrict__ shW, const float2* __restrict__ shE)
{
    const int idx = pos * M + PI;
    const float2 A = a2[idx], B = b2[idx];

    // add = a+b on circle, sub = a-b (conj b) -- share the 4 products
    {
        float t1 = A.x * B.x, t2 = A.y * B.y, t3 = A.y * B.x, t4 = A.x * B.y;
        oAdd[idx] = make_float2(t1 - t2, t3 + t4);
        oSub[idx] = make_float2(t1 + t2, t3 - t4);
    }

    // logits in log2 domain (tables pre-scaled by TEMP*log2e)
    float wa[P], wb[P];
#pragma unroll
    for (int i = 0; i < P; i++) {
        float2 t = shW[OFF + i];
        wa[i] = fmaf(A.x, t.x, A.y * t.y);
        wb[i] = fmaf(B.x, t.x, B.y * t.y);
    }

    // dual-accumulator max per side (FMNMX rides the alu pipe)
    float ma0 = wa[0], mb0 = wb[0];
    float ma1 = (P > 1) ? wa[1] : wa[0];
    float mb1 = (P > 1) ? wb[1] : wb[0];
#pragma unroll
    for (int i = 2; i < P; i++) {
        if (i & 1) { ma1 = fmaxf(ma1, wa[i]); mb1 = fmaxf(mb1, wb[i]); }
        else       { ma0 = fmaxf(ma0, wa[i]); mb0 = fmaxf(mb0, wb[i]); }
    }
    const float mxa = fmaxf(ma0, ma1), mxb = fmaxf(mb0, mb1);

    // exp2 + sums (dual accumulators per side)
    float sa0 = 0.f, sa1 = 0.f, sb0 = 0.f, sb1 = 0.f;
#pragma unroll
    for (int i = 0; i < P; i++) {
        float ea = ex2f(wa[i] - mxa);
        float eb = ex2f(wb[i] - mxb);
        wa[i] = ea; wb[i] = eb;
        if (i & 1) { sa1 += ea; sb1 += eb; }
        else       { sa0 += ea; sb0 += eb; }
    }
    const float Sa = sa0 + sa1, Sb = sb0 + sb1;

    // dist over residues; i=0 / j=0 cross terms collapse onto residue 0
    float dist[P];
    dist[0] = fmaf(wa[0], Sb, fmaf(wb[0], Sa, -(wa[0] * wb[0])));
#pragma unroll
    for (int k = 1; k < P; k++) dist[k] = 0.f;
#pragma unroll
    for (int i = 1; i < P; i++) {
        const float wai = wa[i];
#pragma unroll
        for (int j = 1; j < P; j++) {
            const int k = (i * j) % P;   // bijection over 1..P-1 per i
            dist[k] = fmaf(wai, wb[j], dist[k]);
        }
    }

    // re-encode to circle (4 accumulators), normalize by (sum wa)*(sum wb)
    float X0 = 0.f, X1 = 0.f, Y0 = 0.f, Y1 = 0.f;
#pragma unroll
    for (int k = 0; k < P; k++) {
        float2 e = shE[OFF + k];
        if (k & 1) { X1 = fmaf(dist[k], e.x, X1); Y1 = fmaf(dist[k], e.y, Y1); }
        else       { X0 = fmaf(dist[k], e.x, X0); Y0 = fmaf(dist[k], e.y, Y0); }
    }
    const float inv = rcpf(Sa * Sb);
    oMul[idx] = make_float2((X0 + X1) * inv, (Y0 + Y1) * inv);
}

// One position per thread, all 10 primes (keeps each output cache line owned by
// one thread -> no partial-line RMW, no inter-block prime imbalance).
// blk=64 -> 1024 CTAs (~6.9/SM) for fine-grained wave balancing.
// (64,8) caps at 128 regs; expected actual ~105 (wa[29]+wb[29]+dist[29]).
__global__ void __launch_bounds__(64, 8)
circle_kernel(const float* __restrict__ a, const float* __restrict__ b,
              float* __restrict__ out)
{
    __shared__ float2 shW[NTAB];
    __shared__ float2 shE[NTAB];
    for (int i = threadIdx.x; i < NTAB; i += 64) {
        shW[i] = g_tabW[i];
        shE[i] = g_tabE[i];
    }
    __syncthreads();

    const int pos = blockIdx.x * 64 + threadIdx.x;

    const float2* a2 = (const float2*)a;
    const float2* b2 = (const float2*)b;
    float2* oAdd = (float2*)out;
    float2* oSub = oAdd + (size_t)NPOS * M;
    float2* oMul = oSub + (size_t)NPOS * M;

    // prime offsets into tables: 2:0 3:2 5:5 7:10 11:17 13:28 17:41 19:58 23:77 29:100
    prime_scalar< 2, 0,   0>(pos, a2, b2, oAdd, oSub, oMul, shW, shE);
    prime_scalar< 3, 1,   2>(pos, a2, b2, oAdd, oSub, oMul, shW, shE);
    prime_scalar< 5, 2,   5>(pos, a2, b2, oAdd, oSub, oMul, shW, shE);
    prime_scalar< 7, 3,  10>(pos, a2, b2, oAdd, oSub, oMul, shW, shE);
    prime_scalar<11, 4,  17>(pos, a2, b2, oAdd, oSub, oMul, shW, shE);
    prime_scalar<13, 5,  28>(pos, a2, b2, oAdd, oSub, oMul, shW, shE);
    prime_scalar<17, 6,  41>(pos, a2, b2, oAdd, oSub, oMul, shW, shE);
    prime_scalar<19, 7,  58>(pos, a2, b2, oAdd, oSub, oMul, shW, shE);
    prime_scalar<23, 8,  77>(pos, a2, b2, oAdd, oSub, oMul, shW, shE);
    prime_scalar<29, 9, 100>(pos, a2, b2, oAdd, oSub, oMul, shW, shE);
}

extern "C" void kernel_launch(void* const* d_in, const int* in_sizes, int n_in,
                              void* d_out, int out_size) {
    const float* a = (const float*)d_in[0];
    const float* b = (const float*)d_in[1];
    float* out = (float*)d_out;
    init_tables_kernel<<<1, 160>>>();
    circle_kernel<<<NPOS / 64, 64>>>(a, b, out);
}